// round 1
// baseline (speedup 1.0000x reference)
#include <cuda_runtime.h>
#include <math.h>

#define AN 3
#define NC 20
#define NCH 25          // 5 + NC
#define BATCH 32
#define NTHREADS 256
#define OBJ_BLOCKS 144
#define TOTAL_BLOCKS (OBJ_BLOCKS + 3)

// persistent accumulators (zero-initialized at module load; finalize block
// re-zeros them every run so graph replays start clean)
__device__ double g_acc[3];          // [0]=box_sum, [1]=obj_mean_sum, [2]=cls_sum
__device__ unsigned int g_done;

__device__ __forceinline__ float softplusf(float x) {
    return fmaxf(x, 0.f) + log1pf(expf(-fabsf(x)));
}

__global__ __launch_bounds__(NTHREADS)
void detection_loss_kernel(const float* __restrict__ p0,
                           const float* __restrict__ p1,
                           const float* __restrict__ p2,
                           const float* __restrict__ targets,
                           int N, float* __restrict__ out, int out_size)
{
    const int tid = threadIdx.x;
    const int bid = blockIdx.x;

    // per-scale constants
    const float* preds[3] = {p0, p1, p2};
    const int   Ws[3]  = {80, 40, 20};
    const int   HWs[3] = {6400, 1600, 400};
    const float invC[3] = {1.0f / (BATCH * AN * 6400),
                           1.0f / (BATCH * AN * 1600),
                           1.0f / (BATCH * AN * 400)};

    double lb = 0.0, lo = 0.0, lc = 0.0;

    if (bid < OBJ_BLOCKS) {
        // ---- dense objectness softplus sum over channel-4 planes ----
        // vec4 element counts per scale: 96*HW/4
        const int V0 = BATCH * AN * 6400 / 4;       // 153600
        const int V1 = BATCH * AN * 1600 / 4;       // 38400
        const int V2 = BATCH * AN * 400 / 4;        // 9600
        const int VT = V0 + V1 + V2;                // 201600

        for (int v = bid * NTHREADS + tid; v < VT; v += OBJ_BLOCKS * NTHREADS) {
            int s, rem;
            if (v < V0)            { s = 0; rem = v; }
            else if (v < V0 + V1)  { s = 1; rem = v - V0; }
            else                   { s = 2; rem = v - V0 - V1; }
            const int HWv = HWs[s] >> 2;
            const int plane = rem / HWv;            // 0..95  (b*3 + a)
            const int off   = rem - plane * HWv;
            const int b = plane / AN;
            const int a = plane - b * AN;
            const float4* base = (const float4*)(preds[s]
                                + ((size_t)b * (AN * NCH) + a * NCH + 4) * (size_t)HWs[s]);
            float4 x = base[off];
            float sp = softplusf(x.x) + softplusf(x.y) + softplusf(x.z) + softplusf(x.w);
            lo += (double)sp * (double)invC[s];
        }
    } else {
        // ---- per-target block: one scale per block ----
        const int s  = bid - OBJ_BLOCKS;
        const float* p = preds[s];
        const int W  = Ws[s];
        const int HW = HWs[s];
        const float invcnt = invC[s];
        const float Wf = (float)W;

        __shared__ float st[NTHREADS * 6];
        for (int i = tid; i < N * 6 && i < NTHREADS * 6; i += NTHREADS)
            st[i] = targets[i];
        __syncthreads();

        if (tid < N) {
            const float* t = &st[tid * 6];
            const int bi = (int)t[0];
            const int ci = (int)t[1];
            const float cx = t[2] * Wf;
            const float cy = t[3] * Wf;
            const int gi = (int)fminf(fmaxf(cx, 0.f), Wf - 1.f);
            const int gj = (int)fminf(fmaxf(cy, 0.f), Wf - 1.f);

            // dedup: first occurrence of (bi, gj, gi) owns the obj correction
            bool uniq = true;
            for (int m = 0; m < tid; m++) {
                const float* tm = &st[m * 6];
                int bm  = (int)tm[0];
                int gim = (int)fminf(fmaxf(tm[2] * Wf, 0.f), Wf - 1.f);
                int gjm = (int)fminf(fmaxf(tm[3] * Wf, 0.f), Wf - 1.f);
                if (bm == bi && gim == gi && gjm == gj) { uniq = false; break; }
            }

            const size_t cellbase = (size_t)bi * (AN * NCH) * HW
                                  + (size_t)gj * W + gi;

            // target box (normalized coords)
            const float tw = t[4], th = t[5];
            const float tb0 = t[2] - tw / 2.f, tb1 = t[3] - th / 2.f;
            const float tb2 = t[2] + tw / 2.f, tb3 = t[3] + th / 2.f;
            const float twh = (tw * Wf) / 2.f;   // grid units / 2
            const float thh = (th * Wf) / 2.f;
            const float gif = (float)gi, gjf = (float)gj;

            for (int a = 0; a < AN; a++) {
                const float* cell = p + cellbase + (size_t)a * NCH * HW;
                const float c0 = cell[0];
                const float c1 = cell[(size_t)HW];
                const float sx = 1.f / (1.f + expf(-c0));
                const float sy = 1.f / (1.f + expf(-c1));

                const float pb0 = (sx + gif - twh) / Wf;
                const float pb1 = (sy + gjf - thh) / Wf;
                const float pb2 = (sx + gif + twh) / Wf;
                const float pb3 = (sy + gjf + thh) / Wf;

                // CIoU loss (mirrors reference op-for-op in fp32)
                const float ix1 = fmaxf(pb0, tb0), iy1 = fmaxf(pb1, tb1);
                const float ix2 = fminf(pb2, tb2), iy2 = fminf(pb3, tb3);
                const float inter = fmaxf(ix2 - ix1, 0.f) * fmaxf(iy2 - iy1, 0.f);
                const float area_p = (pb2 - pb0) * (pb3 - pb1);
                const float area_t = (tb2 - tb0) * (tb3 - tb1);
                const float uni = area_p + area_t - inter + 1e-7f;
                const float iou = inter / uni;
                const float ex1 = fminf(pb0, tb0), ey1 = fminf(pb1, tb1);
                const float ex2 = fmaxf(pb2, tb2), ey2 = fmaxf(pb3, tb3);
                const float c2 = (ex2 - ex1) * (ex2 - ex1)
                               + (ey2 - ey1) * (ey2 - ey1) + 1e-7f;
                const float dx = (pb0 + pb2) / 2.f - (tb0 + tb2) / 2.f;
                const float dy = (pb1 + pb3) / 2.f - (tb1 + tb3) / 2.f;
                const float rho2 = dx * dx + dy * dy;
                const float pw  = fmaxf(pb2 - pb0, 1e-7f);
                const float ph  = fmaxf(pb3 - pb1, 1e-7f);
                const float tww = fmaxf(tb2 - tb0, 1e-7f);
                const float thv = fmaxf(tb3 - tb1, 1e-7f);
                const float dv = atanf(tww / thv) - atanf(pw / ph);
                const float v = (4.f / (float)(M_PI * M_PI)) * dv * dv;
                const float alpha = v / (1.f - iou + v + 1e-7f);
                const float ciou = iou - rho2 / c2 - alpha * v;
                lb += (double)(1.f - ciou);

                // objectness correction: BCE(x,1) - BCE(x,0) = -x (unique cells only)
                if (uniq) {
                    const float x4 = cell[(size_t)4 * HW];
                    lo += (double)(-x4) * (double)invcnt;
                }

                // class BCE, mean over NC classes
                float csum = 0.f;
                #pragma unroll
                for (int c = 0; c < NC; c++) {
                    const float x = cell[(size_t)(5 + c) * HW];
                    csum += (c == ci) ? softplusf(-x) : softplusf(x);
                }
                lc += (double)(csum * (1.f / NC));
            }
        }
        __syncthreads();
    }

    // ---- block reduction of the 3 partial sums ----
    __shared__ double red[NTHREADS];
    double vals[3] = {lb, lo, lc};
    for (int k = 0; k < 3; k++) {
        red[tid] = vals[k];
        __syncthreads();
        for (int stp = NTHREADS / 2; stp > 0; stp >>= 1) {
            if (tid < stp) red[tid] += red[tid + stp];
            __syncthreads();
        }
        if (tid == 0 && red[0] != 0.0) atomicAdd(&g_acc[k], red[0]);
        __syncthreads();
    }

    // ---- last-block finalize ----
    __threadfence();
    if (tid == 0) {
        unsigned int ticket = atomicAdd(&g_done, 1u);
        if (ticket == gridDim.x - 1) {
            double box_s = atomicAdd(&g_acc[0], 0.0);
            double obj_s = atomicAdd(&g_acc[1], 0.0);
            double cls_s = atomicAdd(&g_acc[2], 0.0);
            const double num_t = (double)(N * AN * 3);
            const double lbv = box_s / num_t;
            const double lov = obj_s;
            const double lcv = cls_s / num_t;
            if (out_size > 0) out[0] = (float)(0.05 * lbv + 1.0 * lov + 0.5 * lcv);
            if (out_size > 1) out[1] = (float)lbv;
            if (out_size > 2) out[2] = (float)lov;
            if (out_size > 3) out[3] = (float)lcv;
            if (out_size > 4) out[4] = 0.f;
            // reset for next (graph-replayed) run
            g_acc[0] = 0.0; g_acc[1] = 0.0; g_acc[2] = 0.0;
            g_done = 0u;
        }
    }
}

extern "C" void kernel_launch(void* const* d_in, const int* in_sizes, int n_in,
                              void* d_out, int out_size)
{
    const float* p0 = (const float*)d_in[0];
    const float* p1 = (const float*)d_in[1];
    const float* p2 = (const float*)d_in[2];
    const float* targets = (const float*)d_in[3];
    const int N = in_sizes[3] / 6;
    float* out = (float*)d_out;

    detection_loss_kernel<<<TOTAL_BLOCKS, NTHREADS>>>(p0, p1, p2, targets,
                                                      N, out, out_size);
}

// round 2
// speedup vs baseline: 1.9224x; 1.9224x over previous
#include <cuda_runtime.h>
#include <math.h>

#define AN 3
#define NC 20
#define NTHREADS 256
#define TGT_BLOCKS 9
#define S0_BLOCKS 300
#define S1_BLOCKS 75
#define S2_BLOCKS 19
#define TOTAL_BLOCKS (TGT_BLOCKS + S0_BLOCKS + S1_BLOCKS + S2_BLOCKS)
#define PI2_INV4 0.405284734569351f   // 4/pi^2

// persistent accumulators (finalize block re-zeros them each run)
__device__ double g_lb, g_lc;
__device__ double g_lo[32];
__device__ unsigned int g_done;

__device__ __forceinline__ float sp(float x) {   // softplus, 2 MUFU
    return fmaxf(x, 0.f) + __logf(1.f + __expf(-fabsf(x)));
}

// dense objectness softplus sum for one scale; Q = HW/4 (compile-time)
template<int Q, int NV, int NB>
__device__ __forceinline__ float obj_scale_sum(const float4* __restrict__ p4, int rb) {
    float acc = 0.f;
    for (int v = rb * NTHREADS + (int)threadIdx.x; v < NV; v += NB * NTHREADS) {
        const int plane = v / Q;                 // const Q -> magic multiply
        const int off   = v - plane * Q;
        const float4 x  = p4[25 * v - 24 * off + 4 * Q];
        acc += sp(x.x) + sp(x.y) + sp(x.z) + sp(x.w);
    }
    return acc;
}

// returns full-block sum in thread 0 (undefined elsewhere)
__device__ __forceinline__ float block_sum(float v, float* sh) {
    #pragma unroll
    for (int o = 16; o; o >>= 1) v += __shfl_down_sync(0xffffffffu, v, o);
    const int wid = threadIdx.x >> 5, lid = threadIdx.x & 31;
    if (lid == 0) sh[wid] = v;
    __syncthreads();
    if (wid == 0) {
        v = (lid < NTHREADS / 32) ? sh[lid] : 0.f;
        #pragma unroll
        for (int o = 4; o; o >>= 1) v += __shfl_down_sync(0xffffffffu, v, o);
    }
    __syncthreads();   // shared reused by next reduction
    return v;
}

__global__ __launch_bounds__(NTHREADS)
void detection_loss_kernel(const float* __restrict__ p0,
                           const float* __restrict__ p1,
                           const float* __restrict__ p2,
                           const float* __restrict__ targets,
                           int N, float* __restrict__ out, int out_size)
{
    const int tid = threadIdx.x;
    const int bid = blockIdx.x;

    float lb = 0.f, lo = 0.f, lc = 0.f;

    if (bid < TGT_BLOCKS) {
        // ---- one block per (scale, anchor): gather + box/cls/obj-correction ----
        const int s = bid / 3;
        const int a = bid - 3 * s;
        const float* preds[3] = {p0, p1, p2};
        const int   Ws[3]   = {80, 40, 20};
        const int   HWs[3]  = {6400, 1600, 400};
        const float invCs[3] = {1.f / 614400.f, 1.f / 153600.f, 1.f / 38400.f};
        const float* p = preds[s];
        const int W = Ws[s], HW = HWs[s];
        const float invcnt = invCs[s];
        const float Wf = (float)W;

        __shared__ float st[NTHREADS * 6];
        for (int i = tid; i < N * 6; i += NTHREADS) st[i] = targets[i];
        __syncthreads();

        if (tid < N) {
            const float* t = &st[tid * 6];
            const int bi = (int)t[0];
            const int ci = (int)t[1];
            const int gi = (int)fminf(fmaxf(t[2] * Wf, 0.f), Wf - 1.f);
            const int gj = (int)fminf(fmaxf(t[3] * Wf, 0.f), Wf - 1.f);

            // first occurrence of (bi,gj,gi) owns the obj correction
            bool uniq = true;
            for (int m = 0; m < tid; m++) {
                const float* tm = &st[m * 6];
                const int bm  = (int)tm[0];
                const int gim = (int)fminf(fmaxf(tm[2] * Wf, 0.f), Wf - 1.f);
                const int gjm = (int)fminf(fmaxf(tm[3] * Wf, 0.f), Wf - 1.f);
                if (bm == bi && gim == gi && gjm == gj) { uniq = false; break; }
            }

            const float* cell = p + (size_t)bi * (AN * 25) * HW
                                  + (size_t)a * 25 * HW
                                  + (size_t)gj * W + gi;

            const float tw = t[4], th = t[5];
            const float tb0 = t[2] - tw * 0.5f, tb1 = t[3] - th * 0.5f;
            const float tb2 = t[2] + tw * 0.5f, tb3 = t[3] + th * 0.5f;
            const float twh = tw * Wf * 0.5f, thh = th * Wf * 0.5f;
            const float gif = (float)gi, gjf = (float)gj;

            const float c0 = cell[0];
            const float c1 = cell[(size_t)HW];
            const float sx = __fdividef(1.f, 1.f + __expf(-c0));
            const float sy = __fdividef(1.f, 1.f + __expf(-c1));

            const float pb0 = (sx + gif - twh) / Wf;
            const float pb1 = (sy + gjf - thh) / Wf;
            const float pb2 = (sx + gif + twh) / Wf;
            const float pb3 = (sy + gjf + thh) / Wf;

            // CIoU
            const float inter = fmaxf(fminf(pb2, tb2) - fmaxf(pb0, tb0), 0.f)
                              * fmaxf(fminf(pb3, tb3) - fmaxf(pb1, tb1), 0.f);
            const float area_p = (pb2 - pb0) * (pb3 - pb1);
            const float area_t = (tb2 - tb0) * (tb3 - tb1);
            const float iou = inter / (area_p + area_t - inter + 1e-7f);
            const float exw = fmaxf(pb2, tb2) - fminf(pb0, tb0);
            const float exh = fmaxf(pb3, tb3) - fminf(pb1, tb1);
            const float c2 = exw * exw + exh * exh + 1e-7f;
            const float dx = (pb0 + pb2) * 0.5f - (tb0 + tb2) * 0.5f;
            const float dy = (pb1 + pb3) * 0.5f - (tb1 + tb3) * 0.5f;
            const float rho2 = dx * dx + dy * dy;
            const float pw  = fmaxf(pb2 - pb0, 1e-7f);
            const float ph  = fmaxf(pb3 - pb1, 1e-7f);
            const float tww = fmaxf(tb2 - tb0, 1e-7f);
            const float thv = fmaxf(tb3 - tb1, 1e-7f);
            const float dv = atanf(tww / thv) - atanf(pw / ph);
            const float v = PI2_INV4 * dv * dv;
            const float alpha = v / (1.f - iou + v + 1e-7f);
            lb = 1.f - (iou - rho2 / c2 - alpha * v);

            // obj correction: BCE(x,1)-BCE(x,0) = -x for unique target cells
            if (uniq) lo = -cell[(size_t)4 * HW] * invcnt;

            // class BCE (mean over NC)
            float csum = 0.f;
            #pragma unroll
            for (int c = 0; c < NC; c++) {
                const float x = cell[(size_t)(5 + c) * HW];
                csum += (c == ci) ? sp(-x) : sp(x);
            }
            lc = csum * (1.f / NC);
        }
        __syncthreads();
    } else if (bid < TGT_BLOCKS + S0_BLOCKS) {
        lo = obj_scale_sum<1600, 153600, S0_BLOCKS>((const float4*)p0, bid - TGT_BLOCKS)
             * (1.f / 614400.f);
    } else if (bid < TGT_BLOCKS + S0_BLOCKS + S1_BLOCKS) {
        lo = obj_scale_sum<400, 38400, S1_BLOCKS>((const float4*)p1,
             bid - TGT_BLOCKS - S0_BLOCKS) * (1.f / 153600.f);
    } else {
        lo = obj_scale_sum<100, 9600, S2_BLOCKS>((const float4*)p2,
             bid - TGT_BLOCKS - S0_BLOCKS - S1_BLOCKS) * (1.f / 38400.f);
    }

    // ---- block reductions + global accumulation ----
    __shared__ float sh[NTHREADS / 32];
    const float rb = block_sum(lb, sh);
    const float ro = block_sum(lo, sh);
    const float rc = block_sum(lc, sh);
    if (tid == 0) {
        if (rb != 0.f) atomicAdd(&g_lb, (double)rb);
        if (rc != 0.f) atomicAdd(&g_lc, (double)rc);
        if (ro != 0.f) atomicAdd(&g_lo[bid & 31], (double)ro);
    }

    // ---- last-block finalize ----
    __threadfence();
    if (tid == 0) {
        const unsigned int ticket = atomicAdd(&g_done, 1u);
        if (ticket == (unsigned int)(gridDim.x - 1)) {
            double obj_s = 0.0;
            #pragma unroll
            for (int i = 0; i < 32; i++) {
                obj_s += atomicAdd(&g_lo[i], 0.0);
                g_lo[i] = 0.0;
            }
            const double box_s = atomicAdd(&g_lb, 0.0);
            const double cls_s = atomicAdd(&g_lc, 0.0);
            const double num_t = (double)(N * AN * 3);
            const double lbv = box_s / num_t;
            const double lcv = cls_s / num_t;
            if (out_size > 0) out[0] = (float)(0.05 * lbv + obj_s + 0.5 * lcv);
            if (out_size > 1) out[1] = (float)lbv;
            if (out_size > 2) out[2] = (float)obj_s;
            if (out_size > 3) out[3] = (float)lcv;
            if (out_size > 4) out[4] = 0.f;
            g_lb = 0.0; g_lc = 0.0; g_done = 0u;
        }
    }
}

extern "C" void kernel_launch(void* const* d_in, const int* in_sizes, int n_in,
                              void* d_out, int out_size)
{
    const float* p0 = (const float*)d_in[0];
    const float* p1 = (const float*)d_in[1];
    const float* p2 = (const float*)d_in[2];
    const float* targets = (const float*)d_in[3];
    const int N = in_sizes[3] / 6;
    float* out = (float*)d_out;

    detection_loss_kernel<<<TOTAL_BLOCKS, NTHREADS>>>(p0, p1, p2, targets,
                                                      N, out, out_size);
}